// round 13
// baseline (speedup 1.0000x reference)
#include <cuda_runtime.h>
#include <cuda_bf16.h>
#include <math.h>
#include <stdint.h>

// ---------------------------------------------------------------------------
// Problem constants
// ---------------------------------------------------------------------------
constexpr int cB = 2, cS = 4096, cH = 768, cE = 2, cR = 4, cD = 256;
constexpr int cNC = 64, cL = 64;            // scan chunks: 64 chunks x 64 steps
constexpr int cER  = cE * cR;               // 8
constexpr int cBER = cB * cER;              // 16
constexpr int cBS  = cB * cS;               // 8192
constexpr int cKA  = 3072;                  // gate A width (and A buffer stride)
constexpr float cIMP = 0.05f;
constexpr float cEPS = 1e-6f;

// ---------------------------------------------------------------------------
// Device scratch (static: no allocations allowed)
// ---------------------------------------------------------------------------
__device__ float g_sr[cBS * cD];
__device__ float g_si[cBS * cD];
__device__ float g_cer[cBER * cNC * cD];
__device__ float g_cei[cBER * cNC * cD];
__device__ float g_cir[cBER * cNC * cD];
__device__ float g_cii[cBER * cNC * cD];
__device__ float g_S[cBS * cER * 7];        // per (b,s,e,r): 7 d-sums
__device__ float g_Mr[2 * 14 * cH];         // fused Wsh@Wfus complex matrix
__device__ float g_Mi[2 * 14 * cH];
__device__ float g_MpR[8 * 28 * cH];        // mc partials (8 k-segments)
__device__ float g_MpI[8 * 28 * cH];
__device__ float g_bcr[cH];
__device__ float g_bci[cH];
__device__ float g_fur[cBS * cH];           // fp32 fur for final epilogue

// bf16-split GEMM operands (gate)
__device__ __align__(16) __nv_bfloat16 g_Ahi[(size_t)cBS * cKA];  // [x|fur|fui|z]
__device__ __align__(16) __nv_bfloat16 g_Alo[(size_t)cBS * cKA];
__device__ __align__(16) __nv_bfloat16 g_Bg_hi[cH * cKA];         // [n=768][k=3072]
__device__ __align__(16) __nv_bfloat16 g_Bg_lo[cH * cKA];

// ---------------------------------------------------------------------------
// PTX helpers (sm_80-class only: mma.sync / cp.async)
// ---------------------------------------------------------------------------
__device__ __forceinline__ uint32_t smem_u32(const void* p) {
    uint32_t a;
    asm("{ .reg .u64 t; cvta.to.shared.u64 t, %1; cvt.u32.u64 %0, t; }" : "=r"(a) : "l"(p));
    return a;
}

__device__ __forceinline__ void cp_async16(uint32_t dst, const void* src) {
    asm volatile("cp.async.cg.shared.global [%0], [%1], 16;" :: "r"(dst), "l"(src));
}
__device__ __forceinline__ void cp_commit() {
    asm volatile("cp.async.commit_group;" ::: "memory");
}
template <int N>
__device__ __forceinline__ void cp_wait() {
    asm volatile("cp.async.wait_group %0;" :: "n"(N) : "memory");
}

__device__ __forceinline__ void mma_bf16(float* c, const uint32_t* a,
                                         uint32_t b0, uint32_t b1) {
    asm volatile(
        "mma.sync.aligned.m16n8k16.row.col.f32.bf16.bf16.f32 "
        "{%0,%1,%2,%3}, {%4,%5,%6,%7}, {%8,%9}, {%0,%1,%2,%3};"
        : "+f"(c[0]), "+f"(c[1]), "+f"(c[2]), "+f"(c[3])
        : "r"(a[0]), "r"(a[1]), "r"(a[2]), "r"(a[3]), "r"(b0), "r"(b1));
}

// ---------------------------------------------------------------------------
// misc helpers
// ---------------------------------------------------------------------------
__device__ __forceinline__ void lambda_of(const float* __restrict__ ld_,
                                          const float* __restrict__ th_,
                                          int erd, float& lr, float& li) {
    float ld  = ld_[erd];
    float sp  = (ld > 0.f) ? (ld + log1pf(expf(-ld))) : log1pf(expf(ld));
    float mag = expf(-sp);
    float th  = th_[erd];
    lr = mag * cosf(th);
    li = mag * sinf(th);
}
__device__ __forceinline__ float sigmoidf_(float v) { return 1.0f / (1.0f + expf(-v)); }

__device__ __forceinline__ void split_bf16(float v, __nv_bfloat16& hi, __nv_bfloat16& lo) {
    hi = __float2bfloat16(v);
    lo = __float2bfloat16(v - __bfloat162float(hi));
}

// ---------------------------------------------------------------------------
// Prep kernel: x -> bf16 hi/lo into A cols [0,768)
// ---------------------------------------------------------------------------
__global__ void convert_x(const float* __restrict__ x) {
    const int i = blockIdx.x * 256 + threadIdx.x;      // per float4
    const float4 v = ((const float4*)x)[i];
    const int e   = i * 4;
    const int row = e / cH, col = e % cH;
    const size_t o = (size_t)row * cKA + col;
    __nv_bfloat16 h0, l0, h1, l1, h2, l2, h3, l3;
    split_bf16(v.x, h0, l0); split_bf16(v.y, h1, l1);
    split_bf16(v.z, h2, l2); split_bf16(v.w, h3, l3);
    *(__nv_bfloat162*)(g_Ahi + o)     = __nv_bfloat162(h0, h1);
    *(__nv_bfloat162*)(g_Ahi + o + 2) = __nv_bfloat162(h2, h3);
    *(__nv_bfloat162*)(g_Alo + o)     = __nv_bfloat162(l0, l1);
    *(__nv_bfloat162*)(g_Alo + o + 2) = __nv_bfloat162(l2, l3);
}

// ---------------------------------------------------------------------------
// Prep kernel: Wgate (3072x768) -> Bg[n][k] bf16 hi/lo (768x3072), transposed
// ---------------------------------------------------------------------------
__global__ void prep_wgate(const float* __restrict__ Wg) {
    __shared__ float tile[32][33];
    const int k0 = blockIdx.x * 32, n0 = blockIdx.y * 32;
    const int tx = threadIdx.x, ty = threadIdx.y;
    for (int j = ty; j < 32; j += 8)
        tile[j][tx] = Wg[(size_t)(k0 + j) * cH + n0 + tx];
    __syncthreads();
    for (int j = ty; j < 32; j += 8) {
        const float v = tile[tx][j];          // Wg[(k0+tx)*768 + n0+j]
        __nv_bfloat16 h, l; split_bf16(v, h, l);
        const size_t o = (size_t)(n0 + j) * cKA + (k0 + tx);
        g_Bg_hi[o] = h; g_Bg_lo[o] = l;
    }
}

// ---------------------------------------------------------------------------
// sig GEMM — fp32 SIMT (validated path), BK=16.
// sr|si = x(8192x768) @ [Wsig_r | Wsig_i](768x256) + b
// ---------------------------------------------------------------------------
__global__ void sig_gemm(const float* __restrict__ x,
                         const float* __restrict__ Wr, const float* __restrict__ Wi,
                         const float* __restrict__ br, const float* __restrict__ bi) {
    __shared__ float As[16][128];
    __shared__ float Bs[16][128];
    const int bm = blockIdx.y;          // 0..63
    const int bn = blockIdx.x;          // 0..3
    const float* W;  const float* bias; float* out;
    if (bn < 2) { W = Wr; bias = br; out = g_sr; }
    else        { W = Wi; bias = bi; out = g_si; }
    const int ncol0 = (bn & 1) * 128;

    const int tid = threadIdx.x;
    const int tx = tid & 15, ty = tid >> 4;
    const int rowBase = bm * 128;

    const int arow = tid >> 1, acol = (tid & 1) * 8;   // A: 128 rows x 16 k
    const int brow = tid >> 4, bcol = (tid & 15) * 8;  // B: 16 k x 128 n

    float acc[8][8];
#pragma unroll
    for (int i = 0; i < 8; i++)
#pragma unroll
        for (int j = 0; j < 8; j++) acc[i][j] = 0.f;

    for (int k0 = 0; k0 < 768; k0 += 16) {
        float4 av0 = *(const float4*)&x[(rowBase + arow) * 768 + k0 + acol];
        float4 av1 = *(const float4*)&x[(rowBase + arow) * 768 + k0 + acol + 4];
        As[acol + 0][arow] = av0.x;
        As[acol + 1][arow] = av0.y;
        As[acol + 2][arow] = av0.z;
        As[acol + 3][arow] = av0.w;
        As[acol + 4][arow] = av1.x;
        As[acol + 5][arow] = av1.y;
        As[acol + 6][arow] = av1.z;
        As[acol + 7][arow] = av1.w;
        *(float4*)&Bs[brow][bcol]     = *(const float4*)&W[(k0 + brow) * cD + ncol0 + bcol];
        *(float4*)&Bs[brow][bcol + 4] = *(const float4*)&W[(k0 + brow) * cD + ncol0 + bcol + 4];
        __syncthreads();
#pragma unroll
        for (int kk = 0; kk < 16; kk++) {
            float4 a0 = *(const float4*)&As[kk][ty * 8];
            float4 a1 = *(const float4*)&As[kk][ty * 8 + 4];
            float4 b0 = *(const float4*)&Bs[kk][tx * 8];
            float4 b1 = *(const float4*)&Bs[kk][tx * 8 + 4];
            float a[8] = {a0.x, a0.y, a0.z, a0.w, a1.x, a1.y, a1.z, a1.w};
            float b[8] = {b0.x, b0.y, b0.z, b0.w, b1.x, b1.y, b1.z, b1.w};
#pragma unroll
            for (int i = 0; i < 8; i++)
#pragma unroll
                for (int j = 0; j < 8; j++) acc[i][j] += a[i] * b[j];
        }
        __syncthreads();
    }
#pragma unroll
    for (int i = 0; i < 8; i++) {
        int r = rowBase + ty * 8 + i;
#pragma unroll
        for (int j = 0; j < 8; j += 4) {
            int c = ncol0 + tx * 8 + j;
            float4 v;
            v.x = acc[i][j + 0] + bias[c + 0];
            v.y = acc[i][j + 1] + bias[c + 1];
            v.z = acc[i][j + 2] + bias[c + 2];
            v.w = acc[i][j + 3] + bias[c + 3];
            *(float4*)&out[r * cD + c] = v;
        }
    }
}

// ---------------------------------------------------------------------------
// HMMA bf16-split gate GEMM: out = x + sigmoid(A@Bg^T + bg) * fur.
// Manual-LDS fragments. 128x128x32 tile, 8 warps. 4-stage cp.async ring with
// the canonical multistage ordering:
//   wait(stage t) -> barrier -> prefetch(t+3) -> compute(t)
// The prefetch targets buffer (t-1)&3, which is safe because the barrier at
// the top of iteration t retires compute(t-1) on all warps (this ordering is
// the fix for the R12 race where the prefetch preceded the barrier).
// Dynamic smem 80KB, __launch_bounds__(256,2) -> 2 CTAs/SM (160KB <= 228KB).
// ---------------------------------------------------------------------------
constexpr int SSTR   = 40;                    // smem row stride in bf16 (80B)
constexpr int STAGES = 4;
constexpr int STAGE_ELEMS = 128 * SSTR;       // per matrix per stage (bf16)
constexpr int GATE_SMEM_BYTES = STAGES * STAGE_ELEMS * 2 * 2;  // A+B, bf16

__global__ __launch_bounds__(256, 2) void gate_mma(
    const float* __restrict__ x, const float* __restrict__ bg,
    float* __restrict__ out) {
    extern __shared__ __align__(16) __nv_bfloat16 smem[];
    __nv_bfloat16* sA = smem;                          // [STAGES][128*SSTR]
    __nv_bfloat16* sB = smem + STAGES * STAGE_ELEMS;   // [STAGES][128*SSTR]

    const int tid = threadIdx.x;
    const int wid = tid >> 5, lane = tid & 31;
    const int wm = wid >> 2, wn = wid & 3;          // 2 x 4 warp grid
    const int bn = blockIdx.x, bm = blockIdx.y;
    const int rowBase = bm * 128, colBase = bn * 128;

    const uint32_t sA0 = smem_u32(sA);
    const uint32_t sB0 = smem_u32(sB);

    constexpr int nkt = cKA / 32;    // 96
    constexpr int NT  = 3 * nkt;     // 288

    const int lrow = tid >> 1;                      // 0..127
    const int lby  = (tid & 1) * 32;                // byte offset within 64B row

    auto load_tile = [&](int i, int buf) {
        const int term = i / nkt, kt = i - term * nkt;
        const __nv_bfloat16* Asrc = (term == 2) ? g_Alo : g_Ahi;
        const __nv_bfloat16* Bsrc = (term == 1) ? g_Bg_lo : g_Bg_hi;
        const int k0 = kt * 32;
        const char* ga = (const char*)(Asrc + (size_t)(rowBase + lrow) * cKA + k0) + lby;
        const char* gb = (const char*)(Bsrc + (size_t)(colBase + lrow) * cKA + k0) + lby;
        const uint32_t da = sA0 + buf * (STAGE_ELEMS * 2) + lrow * (SSTR * 2) + lby;
        const uint32_t db = sB0 + buf * (STAGE_ELEMS * 2) + lrow * (SSTR * 2) + lby;
        cp_async16(da,      ga);
        cp_async16(da + 16, ga + 16);
        cp_async16(db,      gb);
        cp_async16(db + 16, gb + 16);
    };

    float acc[4][4][4];
#pragma unroll
    for (int mi = 0; mi < 4; mi++)
#pragma unroll
        for (int ni = 0; ni < 4; ni++)
#pragma unroll
            for (int q = 0; q < 4; q++) acc[mi][ni][q] = 0.f;

    // prefetch STAGES-1 stages, one commit group each
#pragma unroll
    for (int s = 0; s < STAGES - 1; s++) {
        load_tile(s, s);
        cp_commit();
    }

    const int fq = lane >> 2;                // fragment row/col group
    const int fk = (lane & 3) * 2;           // fragment k pair base

    for (int t = 0; t < NT; t++) {
        cp_wait<STAGES - 2>();               // stage t's group retired
        __syncthreads();                     // compute(t-1) retired on all warps

        // prefetch stage t+3 into buffer (t-1)&3 — safe after the barrier
        if (t + STAGES - 1 < NT) {
            load_tile(t + STAGES - 1, (t + STAGES - 1) & (STAGES - 1));
            cp_commit();
        }

        const int buf = t & (STAGES - 1);
        const __nv_bfloat16* aBuf = sA + buf * STAGE_ELEMS;
        const __nv_bfloat16* bBuf = sB + buf * STAGE_ELEMS;

#pragma unroll
        for (int ks = 0; ks < 2; ks++) {
            const int kb = ks * 16 + fk;
            uint32_t af[4][4];
#pragma unroll
            for (int mi = 0; mi < 4; mi++) {
                const __nv_bfloat16* p = aBuf + (wm * 64 + mi * 16 + fq) * SSTR + kb;
                af[mi][0] = *(const uint32_t*)p;
                af[mi][1] = *(const uint32_t*)(p + 8 * SSTR);
                af[mi][2] = *(const uint32_t*)(p + 8);
                af[mi][3] = *(const uint32_t*)(p + 8 * SSTR + 8);
            }
            uint32_t bfr[4][2];
#pragma unroll
            for (int ni = 0; ni < 4; ni++) {
                const __nv_bfloat16* p = bBuf + (wn * 32 + ni * 8 + fq) * SSTR + kb;
                bfr[ni][0] = *(const uint32_t*)p;
                bfr[ni][1] = *(const uint32_t*)(p + 8);
            }
#pragma unroll
            for (int mi = 0; mi < 4; mi++)
#pragma unroll
                for (int ni = 0; ni < 4; ni++)
                    mma_bf16(acc[mi][ni], af[mi], bfr[ni][0], bfr[ni][1]);
        }
    }

    // ---- epilogue ----
#pragma unroll
    for (int mi = 0; mi < 4; mi++) {
#pragma unroll
        for (int ni = 0; ni < 4; ni++) {
            const int m0 = rowBase + wm * 64 + mi * 16 + (lane >> 2);
            const int n  = colBase + wn * 32 + ni * 8 + (lane & 3) * 2;
#pragma unroll
            for (int half = 0; half < 2; half++) {
                const int r = m0 + half * 8;
                const float c0 = acc[mi][ni][half * 2 + 0];
                const float c1 = acc[mi][ni][half * 2 + 1];
                const float2 xv = *(const float2*)(x + (size_t)r * cH + n);
                const float2 fv = *(const float2*)(g_fur + (size_t)r * cH + n);
                const float2 bv = *(const float2*)(bg + n);
                float2 ov;
                ov.x = xv.x + fv.x * sigmoidf_(c0 + bv.x);
                ov.y = xv.y + fv.y * sigmoidf_(c1 + bv.y);
                *(float2*)(out + (size_t)r * cH + n) = ov;
            }
        }
    }
}

// ---------------------------------------------------------------------------
// Scan pass1 — per (b,e,r,chunk), local chunk-end state (zero init)
// ---------------------------------------------------------------------------
__global__ void scan_pass1(const float* __restrict__ ld_, const float* __restrict__ th_,
                           const float* __restrict__ Br_, const float* __restrict__ Bi_) {
    const int blk = blockIdx.x;
    const int c   = blk % cNC;
    const int er  = blk / cNC;
    const int b   = er / cER;
    const int erx = er % cER;
    const int d   = threadIdx.x;
    const int erd = erx * cD + d;

    float lr, li; lambda_of(ld_, th_, erd, lr, li);
    const float Br = Br_[erd], Bi = Bi_[erd];

    float hr = 0.f, hi = 0.f;
    const int t0 = c * cL;
    for (int t = t0; t < t0 + cL; t++) {
        float xr = g_sr[(b * cS + t) * cD + d];
        float xi = g_si[(b * cS + t) * cD + d];
        float ur = Br * xr - Bi * xi;
        float ui = Br * xi + Bi * xr;
        float nr = lr * hr - li * hi + ur;
        float ni = lr * hi + li * hr + ui;
        hr = nr; hi = ni;
    }
    const int idx = (er * cNC + c) * cD + d;
    g_cer[idx] = hr;
    g_cei[idx] = hi;
}

// ---------------------------------------------------------------------------
// Scan pass2 — serial combine across chunks per channel
// ---------------------------------------------------------------------------
__global__ void scan_pass2(const float* __restrict__ ld_, const float* __restrict__ th_) {
    const int gid = blockIdx.x * blockDim.x + threadIdx.x;
    const int d   = gid & (cD - 1);
    const int er  = gid >> 8;
    const int erx = er % cER;
    const int erd = erx * cD + d;

    float lr, li; lambda_of(ld_, th_, erd, lr, li);
    float ar = lr, ai = li;
#pragma unroll
    for (int q = 0; q < 6; q++) {
        float nr = ar * ar - ai * ai;
        float ni = 2.f * ar * ai;
        ar = nr; ai = ni;
    }
    float Sr = 0.f, Si = 0.f;
    for (int c = 0; c < cNC; c++) {
        const int idx = (er * cNC + c) * cD + d;
        g_cir[idx] = Sr;
        g_cii[idx] = Si;
        float nr = ar * Sr - ai * Si + g_cer[idx];
        float ni = ar * Si + ai * Sr + g_cei[idx];
        Sr = nr; Si = ni;
    }
}

// ---------------------------------------------------------------------------
// Scan pass3 — replay with carry, fused normalize + twist + 7 d-sums.
// Double-buffered smem reductions: ONE __syncthreads per timestep.
// ---------------------------------------------------------------------------
__global__ void scan_pass3(const float* __restrict__ ld_, const float* __restrict__ th_,
                           const float* __restrict__ Br_, const float* __restrict__ Bi_) {
    const int blk = blockIdx.x;
    const int c   = blk % cNC;
    const int er  = blk / cNC;
    const int b   = er / cER;
    const int erx = er % cER;
    const int d   = threadIdx.x;
    const int erd = erx * cD + d;
    const int lane = d & 31, warp = d >> 5;

    float lr, li; lambda_of(ld_, th_, erd, lr, li);
    const float Br = Br_[erd], Bi = Bi_[erd];

    const int cidx = (er * cNC + c) * cD + d;
    float hr = g_cir[cidx], hi = g_cii[cidx];

    __shared__ float sredp[2][8];
    __shared__ float sred7[2][8][7];

    const int t0 = c * cL;
    const int sbase = (b * cS) * (cER * 7) + erx * 7 + d;   // valid only d<7
    for (int t = t0; t < t0 + cL; t++) {
        float xr = g_sr[(b * cS + t) * cD + d];
        float xi = g_si[(b * cS + t) * cD + d];
        float ur = Br * xr - Bi * xi;
        float ui = Br * xi + Bi * xr;
        float nhr = lr * hr - li * hi + ur;
        float nhi = lr * hi + li * hr + ui;
        hr = nhr; hi = nhi;

        float v = hr * hr + hi * hi;
#pragma unroll
        for (int off = 16; off > 0; off >>= 1) v += __shfl_xor_sync(0xffffffffu, v, off);
        if (lane == 0) sredp[t & 1][warp] = v;
        __syncthreads();                        // publishes sredp[t&1] AND sred7[(t-1)&1]
        float tot = 0.f;
#pragma unroll
        for (int w = 0; w < 8; w++) tot += sredp[t & 1][w];
        const float inv = rsqrtf(tot * (1.0f / cD) + cEPS);

        const float nr = hr * inv, ni = hi * inv;
        const float thr_ = tanhf(nr), thi_ = tanhf(ni);
        const float gr_ = nr * (1.f + cIMP * thi_);
        const float gi_ = ni * (1.f + cIMP * thr_);

        float s[7];
        s[0] = gr_;          s[1] = gi_;
        s[2] = gr_ * gr_;    s[3] = gi_ * gi_;
        s[4] = gr_ * gi_;
        s[5] = tanhf(gr_);   s[6] = tanhf(gi_);
#pragma unroll
        for (int k = 0; k < 7; k++) {
            float u = s[k];
#pragma unroll
            for (int off = 16; off > 0; off >>= 1) u += __shfl_xor_sync(0xffffffffu, u, off);
            if (lane == 0) sred7[t & 1][warp][k] = u;
        }
        // readback for PREVIOUS timestep (its writes were published by this sync)
        if (t > t0 && d < 7) {
            const int tp = t - 1;
            float tk = 0.f;
#pragma unroll
            for (int w = 0; w < 8; w++) tk += sred7[tp & 1][w][d];
            g_S[sbase + tp * (cER * 7)] = tk;
        }
    }
    __syncthreads();
    if (d < 7) {
        const int tp = t0 + cL - 1;
        float tk = 0.f;
#pragma unroll
        for (int w = 0; w < 8; w++) tk += sred7[tp & 1][w][d];
        g_S[sbase + tp * (cER * 7)] = tk;
    }
}

// ---------------------------------------------------------------------------
// Mc = Wsh (complex) @ Wfus (complex) — 8-way k-split + reduce
// ---------------------------------------------------------------------------
__global__ void mc_part(const float* __restrict__ Wsh_r, const float* __restrict__ Wsh_i,
                        const float* __restrict__ Wfus_r, const float* __restrict__ Wfus_i) {
    const int j = blockIdx.x;      // e*14 + f
    const int seg = blockIdx.y;    // 0..7
    const int e = j / 14;
    const int tid = threadIdx.x;
    const float* wr = &Wsh_r[j * cH];
    const float* wi = &Wsh_i[j * cH];
    float accr[3] = {0.f, 0.f, 0.f}, acci[3] = {0.f, 0.f, 0.f};
    const int h0 = seg * 96;
    for (int h = h0; h < h0 + 96; h++) {
        const float ar = wr[h], ai = wi[h];
        const float* fr_row = &Wfus_r[(size_t)(e * cH + h) * cH];
        const float* fi_row = &Wfus_i[(size_t)(e * cH + h) * cH];
#pragma unroll
        for (int q = 0; q < 3; q++) {
            const int col = tid + q * 256;
            const float br = fr_row[col], bi = fi_row[col];
            accr[q] += ar * br - ai * bi;
            acci[q] += ar * bi + ai * br;
        }
    }
#pragma unroll
    for (int q = 0; q < 3; q++) {
        g_MpR[(seg * 28 + j) * cH + tid + q * 256] = accr[q];
        g_MpI[(seg * 28 + j) * cH + tid + q * 256] = acci[q];
    }
}

__global__ void mc_reduce() {
    const int idx = blockIdx.x * 256 + threadIdx.x;   // 28*768 = 21504
    const int j = idx / cH, col = idx % cH;
    float ar = 0.f, ai = 0.f;
#pragma unroll
    for (int seg = 0; seg < 8; seg++) {
        ar += g_MpR[(seg * 28 + j) * cH + col];
        ai += g_MpI[(seg * 28 + j) * cH + col];
    }
    g_Mr[j * cH + col] = ar;
    g_Mi[j * cH + col] = ai;
}

// ---------------------------------------------------------------------------
// bc = bfus + bsh(complex) @ Wfus(complex)
// ---------------------------------------------------------------------------
__global__ void bc_kernel(const float* __restrict__ bsh_r, const float* __restrict__ bsh_i,
                          const float* __restrict__ Wfus_r, const float* __restrict__ Wfus_i,
                          const float* __restrict__ bfus_r, const float* __restrict__ bfus_i) {
    const int c = blockIdx.x * blockDim.x + threadIdx.x;
    if (c >= cH) return;
    float ar = bfus_r[c], ai = bfus_i[c];
    for (int k = 0; k < cE * cH; k++) {
        const float br = bsh_r[k], bi = bsh_i[k];
        const float wr = Wfus_r[(size_t)k * cH + c], wi = Wfus_i[(size_t)k * cH + c];
        ar += br * wr - bi * wi;
        ai += br * wi + bi * wr;
    }
    g_bcr[c] = ar;
    g_bci[c] = ai;
}

// ---------------------------------------------------------------------------
// fuse — features from g_S, complex GEMM (K=28) with Mc; writes fur (fp32)
// and bf16 hi/lo splits of fur/fui/z into A cols [768, 3072).
// ---------------------------------------------------------------------------
__global__ void fuse_kernel() {
    const int bs0 = blockIdx.x * 8;
    const int tid = threadIdx.x;

    __shared__ float Sh[8][56];
    __shared__ float frs[8][28], fis[8][28];

    for (int i = tid; i < 8 * 56; i += 256) {
        const int row = i / 56, q = i % 56;
        Sh[row][q] = g_S[(bs0 + row) * 56 + q];
    }
    __syncthreads();

    if (tid < 8 * 28) {
        const int row = tid / 28, j = tid % 28;
        const int e = j / 14, idx = j % 14;
        const float* Se = &Sh[row][e * 28];
        const float invD  = 1.0f / cD;
        const float invRD = 1.0f / (cR * cD);
        float fr = 0.f, fi = 0.f;
        if (idx < 4) {
            fr = Se[idx * 7 + 0] * invD;
            fi = Se[idx * 7 + 1] * invD;
        } else if (idx < 8) {
            const int r = idx - 4;
            fr = (Se[r * 7 + 2] - Se[r * 7 + 3]) * invD;
            fi = 2.f * Se[r * 7 + 4] * invD;
        } else {
            float T[7];
#pragma unroll
            for (int k = 0; k < 7; k++)
                T[k] = Se[k] + Se[7 + k] + Se[14 + k] + Se[21 + k];
            switch (idx) {
                case 8:  fr = T[0] * invRD;              fi = T[1] * invRD;              break;
                case 9:  fr = (T[2] - T[3]) * invRD;     fi = 2.f * T[4] * invRD;        break;
                case 10: fr = (T[2] + T[3]) * invRD;     fi = 0.f;                       break;
                case 11: fr = T[5] * invRD;              fi = T[6] * invRD;              break;
                case 12: fr = sqrtf(T[2] * invRD + cEPS); fi = sqrtf(T[3] * invRD + cEPS); break;
                default: fr = T[4] * invRD;              fi = 0.f;                       break;
            }
        }
        frs[row][j] = fr;
        fis[row][j] = fi;
    }
    __syncthreads();

    float ar[8][3], ai[8][3];
#pragma unroll
    for (int r = 0; r < 8; r++)
#pragma unroll
        for (int q = 0; q < 3; q++) { ar[r][q] = 0.f; ai[r][q] = 0.f; }

    for (int j = 0; j < 28; j++) {
        float mr[3], mi[3];
#pragma unroll
        for (int q = 0; q < 3; q++) {
            const int c = tid + q * 256;
            mr[q] = g_Mr[j * cH + c];
            mi[q] = g_Mi[j * cH + c];
        }
#pragma unroll
        for (int row = 0; row < 8; row++) {
            const float fr = frs[row][j], fi = fis[row][j];
#pragma unroll
            for (int q = 0; q < 3; q++) {
                ar[row][q] += fr * mr[q] - fi * mi[q];
                ai[row][q] += fr * mi[q] + fi * mr[q];
            }
        }
    }

#pragma unroll
    for (int q = 0; q < 3; q++) {
        const int c = tid + q * 256;
        const float bcr = g_bcr[c], bci = g_bci[c];
#pragma unroll
        for (int row = 0; row < 8; row++) {
            const float fur = ar[row][q] + bcr;
            const float fui = ai[row][q] + bci;
            const float z   = fur * (fui * sigmoidf_(fui));
            const size_t o  = (size_t)(bs0 + row) * cH + c;
            g_fur[o] = fur;
            const size_t ao = (size_t)(bs0 + row) * cKA;
            __nv_bfloat16 h, l;
            split_bf16(fur, h, l); g_Ahi[ao + 768 + c]  = h; g_Alo[ao + 768 + c]  = l;
            split_bf16(fui, h, l); g_Ahi[ao + 1536 + c] = h; g_Alo[ao + 1536 + c] = l;
            split_bf16(z,   h, l); g_Ahi[ao + 2304 + c] = h; g_Alo[ao + 2304 + c] = l;
        }
    }
}

// ---------------------------------------------------------------------------
// launch
// ---------------------------------------------------------------------------
extern "C" void kernel_launch(void* const* d_in, const int* in_sizes, int n_in,
                              void* d_out, int out_size) {
    (void)in_sizes; (void)n_in; (void)out_size;
    const float* x       = (const float*)d_in[0];
    const float* Wsig_r  = (const float*)d_in[1];
    const float* Wsig_i  = (const float*)d_in[2];
    const float* bsig_r  = (const float*)d_in[3];
    const float* bsig_i  = (const float*)d_in[4];
    const float* log_dec = (const float*)d_in[5];
    const float* theta   = (const float*)d_in[6];
    const float* Bin_r   = (const float*)d_in[7];
    const float* Bin_i   = (const float*)d_in[8];
    const float* Wsh_r   = (const float*)d_in[9];
    const float* Wsh_i   = (const float*)d_in[10];
    const float* bsh_r   = (const float*)d_in[11];
    const float* bsh_i   = (const float*)d_in[12];
    const float* Wfus_r  = (const float*)d_in[13];
    const float* Wfus_i  = (const float*)d_in[14];
    const float* bfus_r  = (const float*)d_in[15];
    const float* bfus_i  = (const float*)d_in[16];
    const float* Wgate   = (const float*)d_in[17];
    const float* bgate   = (const float*)d_in[18];
    float* out = (float*)d_out;

    // allow 80KB dynamic smem for the 4-stage gate pipeline (host attr, no alloc)
    cudaFuncSetAttribute(gate_mma, cudaFuncAttributeMaxDynamicSharedMemorySize,
                         GATE_SMEM_BYTES);

    convert_x<<<cBS * cH / 4 / 256, 256>>>(x);
    prep_wgate<<<dim3(cKA / 32, cH / 32), dim3(32, 8)>>>(Wgate);

    // sig via validated fp32 SIMT GEMM (BK=16)
    sig_gemm<<<dim3(4, 64), 256>>>(x, Wsig_r, Wsig_i, bsig_r, bsig_i);

    scan_pass1<<<cBER * cNC, 256>>>(log_dec, theta, Bin_r, Bin_i);
    scan_pass2<<<cBER, 256>>>(log_dec, theta);
    scan_pass3<<<cBER * cNC, 256>>>(log_dec, theta, Bin_r, Bin_i);

    mc_part<<<dim3(28, 8), 256>>>(Wsh_r, Wsh_i, Wfus_r, Wfus_i);
    mc_reduce<<<28 * cH / 256, 256>>>();
    bc_kernel<<<3, 256>>>(bsh_r, bsh_i, Wfus_r, Wfus_i, bfus_r, bfus_i);
    fuse_kernel<<<cBS / 8, 256>>>();

    // gate: out = x + sigmoid([x|fur|fui|z] @ Wgate + bgate) * fur
    gate_mma<<<dim3(6, 64), 256, GATE_SMEM_BYTES>>>(x, bgate, out);
}

// round 14
// speedup vs baseline: 1.1523x; 1.1523x over previous
#include <cuda_runtime.h>
#include <cuda_bf16.h>
#include <math.h>
#include <stdint.h>

// ---------------------------------------------------------------------------
// Problem constants
// ---------------------------------------------------------------------------
constexpr int cB = 2, cS = 4096, cH = 768, cE = 2, cR = 4, cD = 256;
constexpr int cNC = 64, cL = 64;            // scan chunks: 64 chunks x 64 steps
constexpr int cER  = cE * cR;               // 8
constexpr int cBER = cB * cER;              // 16
constexpr int cBS  = cB * cS;               // 8192
constexpr int cKA  = 3072;                  // gate A width (and A buffer stride)
constexpr float cIMP = 0.05f;
constexpr float cEPS = 1e-6f;

// ---------------------------------------------------------------------------
// Device scratch (static: no allocations allowed)
// ---------------------------------------------------------------------------
__device__ float g_sr[cBS * cD];
__device__ float g_si[cBS * cD];
__device__ float g_cer[cBER * cNC * cD];
__device__ float g_cei[cBER * cNC * cD];
__device__ float g_cir[cBER * cNC * cD];
__device__ float g_cii[cBER * cNC * cD];
__device__ float g_S[cBS * cER * 7];        // per (b,s,e,r): 7 d-sums
__device__ float g_Mr[2 * 14 * cH];         // fused Wsh@Wfus complex matrix
__device__ float g_Mi[2 * 14 * cH];
__device__ float g_MpR[8 * 28 * cH];        // mc partials (8 k-segments)
__device__ float g_MpI[8 * 28 * cH];
__device__ float g_bcr[cH];
__device__ float g_bci[cH];
__device__ float g_fur[cBS * cH];           // fp32 fur for final epilogue

// tf32 GEMM operands (gate): A = [x|fur|fui|z], B = Wgate^T, both tf32-rounded
__device__ __align__(16) float g_Atf[(size_t)cBS * cKA];   // [8192][3072]
__device__ __align__(16) float g_Btf[cH * cKA];            // [n=768][k=3072]

// ---------------------------------------------------------------------------
// PTX helpers (sm_80-class only: mma.sync / cp.async / cvt.tf32)
// ---------------------------------------------------------------------------
__device__ __forceinline__ uint32_t smem_u32(const void* p) {
    uint32_t a;
    asm("{ .reg .u64 t; cvta.to.shared.u64 t, %1; cvt.u32.u64 %0, t; }" : "=r"(a) : "l"(p));
    return a;
}

__device__ __forceinline__ void cp_async16(uint32_t dst, const void* src) {
    asm volatile("cp.async.cg.shared.global [%0], [%1], 16;" :: "r"(dst), "l"(src));
}
__device__ __forceinline__ void cp_commit() {
    asm volatile("cp.async.commit_group;" ::: "memory");
}
template <int N>
__device__ __forceinline__ void cp_wait() {
    asm volatile("cp.async.wait_group %0;" :: "n"(N) : "memory");
}

// tf32 m16n8k8 mma: A 4 regs, B 2 regs, C 4 regs fp32
__device__ __forceinline__ void mma_tf32(float* c, const uint32_t* a,
                                         uint32_t b0, uint32_t b1) {
    asm volatile(
        "mma.sync.aligned.m16n8k8.row.col.f32.tf32.tf32.f32 "
        "{%0,%1,%2,%3}, {%4,%5,%6,%7}, {%8,%9}, {%0,%1,%2,%3};"
        : "+f"(c[0]), "+f"(c[1]), "+f"(c[2]), "+f"(c[3])
        : "r"(a[0]), "r"(a[1]), "r"(a[2]), "r"(a[3]), "r"(b0), "r"(b1));
}

__device__ __forceinline__ float tf32_round(float v) {
    uint32_t r;
    asm("cvt.rna.tf32.f32 %0, %1;" : "=r"(r) : "f"(v));
    return __uint_as_float(r);
}

// ---------------------------------------------------------------------------
// misc helpers
// ---------------------------------------------------------------------------
__device__ __forceinline__ void lambda_of(const float* __restrict__ ld_,
                                          const float* __restrict__ th_,
                                          int erd, float& lr, float& li) {
    float ld  = ld_[erd];
    float sp  = (ld > 0.f) ? (ld + log1pf(expf(-ld))) : log1pf(expf(ld));
    float mag = expf(-sp);
    float th  = th_[erd];
    lr = mag * cosf(th);
    li = mag * sinf(th);
}
__device__ __forceinline__ float sigmoidf_(float v) { return 1.0f / (1.0f + expf(-v)); }

// ---------------------------------------------------------------------------
// Prep kernel: x -> tf32-rounded fp32 into A cols [0,768)
// ---------------------------------------------------------------------------
__global__ void convert_x(const float* __restrict__ x) {
    const int i = blockIdx.x * 256 + threadIdx.x;      // per float4
    const float4 v = ((const float4*)x)[i];
    const int e   = i * 4;
    const int row = e / cH, col = e % cH;
    const size_t o = (size_t)row * cKA + col;
    float4 q;
    q.x = tf32_round(v.x); q.y = tf32_round(v.y);
    q.z = tf32_round(v.z); q.w = tf32_round(v.w);
    *(float4*)(g_Atf + o) = q;
}

// ---------------------------------------------------------------------------
// Prep kernel: Wgate (3072x768) -> Btf[n][k] tf32-rounded (768x3072), transposed
// ---------------------------------------------------------------------------
__global__ void prep_wgate(const float* __restrict__ Wg) {
    __shared__ float tile[32][33];
    const int k0 = blockIdx.x * 32, n0 = blockIdx.y * 32;
    const int tx = threadIdx.x, ty = threadIdx.y;
    for (int j = ty; j < 32; j += 8)
        tile[j][tx] = Wg[(size_t)(k0 + j) * cH + n0 + tx];
    __syncthreads();
    for (int j = ty; j < 32; j += 8) {
        const float v = tile[tx][j];          // Wg[(k0+tx)*768 + n0+j]
        g_Btf[(size_t)(n0 + j) * cKA + (k0 + tx)] = tf32_round(v);
    }
}

// ---------------------------------------------------------------------------
// sig GEMM — fp32 SIMT (validated path), BK=16.
// sr|si = x(8192x768) @ [Wsig_r | Wsig_i](768x256) + b
// ---------------------------------------------------------------------------
__global__ void sig_gemm(const float* __restrict__ x,
                         const float* __restrict__ Wr, const float* __restrict__ Wi,
                         const float* __restrict__ br, const float* __restrict__ bi) {
    __shared__ float As[16][128];
    __shared__ float Bs[16][128];
    const int bm = blockIdx.y;          // 0..63
    const int bn = blockIdx.x;          // 0..3
    const float* W;  const float* bias; float* out;
    if (bn < 2) { W = Wr; bias = br; out = g_sr; }
    else        { W = Wi; bias = bi; out = g_si; }
    const int ncol0 = (bn & 1) * 128;

    const int tid = threadIdx.x;
    const int tx = tid & 15, ty = tid >> 4;
    const int rowBase = bm * 128;

    const int arow = tid >> 1, acol = (tid & 1) * 8;   // A: 128 rows x 16 k
    const int brow = tid >> 4, bcol = (tid & 15) * 8;  // B: 16 k x 128 n

    float acc[8][8];
#pragma unroll
    for (int i = 0; i < 8; i++)
#pragma unroll
        for (int j = 0; j < 8; j++) acc[i][j] = 0.f;

    for (int k0 = 0; k0 < 768; k0 += 16) {
        float4 av0 = *(const float4*)&x[(rowBase + arow) * 768 + k0 + acol];
        float4 av1 = *(const float4*)&x[(rowBase + arow) * 768 + k0 + acol + 4];
        As[acol + 0][arow] = av0.x;
        As[acol + 1][arow] = av0.y;
        As[acol + 2][arow] = av0.z;
        As[acol + 3][arow] = av0.w;
        As[acol + 4][arow] = av1.x;
        As[acol + 5][arow] = av1.y;
        As[acol + 6][arow] = av1.z;
        As[acol + 7][arow] = av1.w;
        *(float4*)&Bs[brow][bcol]     = *(const float4*)&W[(k0 + brow) * cD + ncol0 + bcol];
        *(float4*)&Bs[brow][bcol + 4] = *(const float4*)&W[(k0 + brow) * cD + ncol0 + bcol + 4];
        __syncthreads();
#pragma unroll
        for (int kk = 0; kk < 16; kk++) {
            float4 a0 = *(const float4*)&As[kk][ty * 8];
            float4 a1 = *(const float4*)&As[kk][ty * 8 + 4];
            float4 b0 = *(const float4*)&Bs[kk][tx * 8];
            float4 b1 = *(const float4*)&Bs[kk][tx * 8 + 4];
            float a[8] = {a0.x, a0.y, a0.z, a0.w, a1.x, a1.y, a1.z, a1.w};
            float b[8] = {b0.x, b0.y, b0.z, b0.w, b1.x, b1.y, b1.z, b1.w};
#pragma unroll
            for (int i = 0; i < 8; i++)
#pragma unroll
                for (int j = 0; j < 8; j++) acc[i][j] += a[i] * b[j];
        }
        __syncthreads();
    }
#pragma unroll
    for (int i = 0; i < 8; i++) {
        int r = rowBase + ty * 8 + i;
#pragma unroll
        for (int j = 0; j < 8; j += 4) {
            int c = ncol0 + tx * 8 + j;
            float4 v;
            v.x = acc[i][j + 0] + bias[c + 0];
            v.y = acc[i][j + 1] + bias[c + 1];
            v.z = acc[i][j + 2] + bias[c + 2];
            v.w = acc[i][j + 3] + bias[c + 3];
            *(float4*)&out[r * cD + c] = v;
        }
    }
}

// ---------------------------------------------------------------------------
// tf32 single-pass gate GEMM: out = x + sigmoid(A@B^T + bg) * fur.
// A (8192x3072) tf32, B (768x3072) tf32 K-major. 128x128x32 CTA tile, 8 warps
// (2x4), warp tile 64x32. mma.m16n8k8: per 8-k chunk A frag = 4 LDS.32
// (row=lane/4 [+8], k=lane%4 [+4]), B frag = 2 LDS.32 (col=lane/4, k=lane%4
// [+4]). Smem row stride 36 words -> (lane/4)*36+lane%4 == lane mod 32:
// conflict-free. 2-stage cp.async, R13-canonical ordering
// (wait -> barrier -> prefetch -> compute).
// ---------------------------------------------------------------------------
constexpr int S4 = 36;                         // smem row stride in words (144B)
constexpr int TSTAGE = 128 * S4;               // words per matrix per stage
constexpr int GATE_SMEM_BYTES = 2 * TSTAGE * 2 * 4;   // 2 stages x (A+B) x fp32

__global__ __launch_bounds__(256, 2) void gate_tf32(
    const float* __restrict__ x, const float* __restrict__ bg,
    float* __restrict__ out) {
    extern __shared__ __align__(16) float smem[];
    float* sA = smem;                  // [2][128*S4]
    float* sB = smem + 2 * TSTAGE;     // [2][128*S4]

    const int tid = threadIdx.x;
    const int wid = tid >> 5, lane = tid & 31;
    const int wm = wid >> 2, wn = wid & 3;          // 2 x 4 warp grid
    const int bn = blockIdx.x, bm = blockIdx.y;
    const int rowBase = bm * 128, colBase = bn * 128;

    const uint32_t sA0 = smem_u32(sA);
    const uint32_t sB0 = smem_u32(sB);

    constexpr int NT = cKA / 32;       // 96

    // global->smem: 2 threads per row, 16 floats (64B) each
    const int lrow = tid >> 1;
    const int lhw  = (tid & 1) * 16;   // float offset within 32-float row

    auto load_tile = [&](int t, int buf) {
        const int k0 = t * 32;
        const float* ga = g_Atf + (size_t)(rowBase + lrow) * cKA + k0 + lhw;
        const float* gb = g_Btf + (size_t)(colBase + lrow) * cKA + k0 + lhw;
        const uint32_t da = sA0 + (buf * TSTAGE + lrow * S4 + lhw) * 4;
        const uint32_t db = sB0 + (buf * TSTAGE + lrow * S4 + lhw) * 4;
#pragma unroll
        for (int q = 0; q < 4; q++) {
            cp_async16(da + q * 16, ga + q * 4);
            cp_async16(db + q * 16, gb + q * 4);
        }
    };

    float acc[4][4][4];
#pragma unroll
    for (int mi = 0; mi < 4; mi++)
#pragma unroll
        for (int ni = 0; ni < 4; ni++)
#pragma unroll
            for (int q = 0; q < 4; q++) acc[mi][ni][q] = 0.f;

    load_tile(0, 0);
    cp_commit();

    const int fq = lane >> 2;          // 0..7
    const int fk = lane & 3;           // 0..3

    for (int t = 0; t < NT; t++) {
        cp_wait<0>();
        __syncthreads();               // compute(t-1) retired; stage t landed
        if (t + 1 < NT) {
            load_tile(t + 1, (t + 1) & 1);
            cp_commit();
        }

        const float* aBuf = sA + (t & 1) * TSTAGE;
        const float* bBuf = sB + (t & 1) * TSTAGE;

#pragma unroll
        for (int kc = 0; kc < 4; kc++) {
            const int kb = kc * 8 + fk;
            uint32_t af[4][4];
#pragma unroll
            for (int mi = 0; mi < 4; mi++) {
                const float* p = aBuf + (wm * 64 + mi * 16 + fq) * S4 + kb;
                af[mi][0] = __float_as_uint(p[0]);
                af[mi][1] = __float_as_uint(p[8 * S4]);
                af[mi][2] = __float_as_uint(p[4]);
                af[mi][3] = __float_as_uint(p[8 * S4 + 4]);
            }
            uint32_t bf[4][2];
#pragma unroll
            for (int ni = 0; ni < 4; ni++) {
                const float* p = bBuf + (wn * 32 + ni * 8 + fq) * S4 + kb;
                bf[ni][0] = __float_as_uint(p[0]);
                bf[ni][1] = __float_as_uint(p[4]);
            }
#pragma unroll
            for (int mi = 0; mi < 4; mi++)
#pragma unroll
                for (int ni = 0; ni < 4; ni++)
                    mma_tf32(acc[mi][ni], af[mi], bf[ni][0], bf[ni][1]);
        }
    }

    // ---- epilogue (C fragment layout identical to m16n8k16) ----
#pragma unroll
    for (int mi = 0; mi < 4; mi++) {
#pragma unroll
        for (int ni = 0; ni < 4; ni++) {
            const int m0 = rowBase + wm * 64 + mi * 16 + (lane >> 2);
            const int n  = colBase + wn * 32 + ni * 8 + (lane & 3) * 2;
#pragma unroll
            for (int half = 0; half < 2; half++) {
                const int r = m0 + half * 8;
                const float c0 = acc[mi][ni][half * 2 + 0];
                const float c1 = acc[mi][ni][half * 2 + 1];
                const float2 xv = *(const float2*)(x + (size_t)r * cH + n);
                const float2 fv = *(const float2*)(g_fur + (size_t)r * cH + n);
                const float2 bv = *(const float2*)(bg + n);
                float2 ov;
                ov.x = xv.x + fv.x * sigmoidf_(c0 + bv.x);
                ov.y = xv.y + fv.y * sigmoidf_(c1 + bv.y);
                *(float2*)(out + (size_t)r * cH + n) = ov;
            }
        }
    }
}

// ---------------------------------------------------------------------------
// Scan pass1 — per (b,e,r,chunk), local chunk-end state (zero init)
// ---------------------------------------------------------------------------
__global__ void scan_pass1(const float* __restrict__ ld_, const float* __restrict__ th_,
                           const float* __restrict__ Br_, const float* __restrict__ Bi_) {
    const int blk = blockIdx.x;
    const int c   = blk % cNC;
    const int er  = blk / cNC;
    const int b   = er / cER;
    const int erx = er % cER;
    const int d   = threadIdx.x;
    const int erd = erx * cD + d;

    float lr, li; lambda_of(ld_, th_, erd, lr, li);
    const float Br = Br_[erd], Bi = Bi_[erd];

    float hr = 0.f, hi = 0.f;
    const int t0 = c * cL;
    for (int t = t0; t < t0 + cL; t++) {
        float xr = g_sr[(b * cS + t) * cD + d];
        float xi = g_si[(b * cS + t) * cD + d];
        float ur = Br * xr - Bi * xi;
        float ui = Br * xi + Bi * xr;
        float nr = lr * hr - li * hi + ur;
        float ni = lr * hi + li * hr + ui;
        hr = nr; hi = ni;
    }
    const int idx = (er * cNC + c) * cD + d;
    g_cer[idx] = hr;
    g_cei[idx] = hi;
}

// ---------------------------------------------------------------------------
// Scan pass2 — serial combine across chunks per channel
// ---------------------------------------------------------------------------
__global__ void scan_pass2(const float* __restrict__ ld_, const float* __restrict__ th_) {
    const int gid = blockIdx.x * blockDim.x + threadIdx.x;
    const int d   = gid & (cD - 1);
    const int er  = gid >> 8;
    const int erx = er % cER;
    const int erd = erx * cD + d;

    float lr, li; lambda_of(ld_, th_, erd, lr, li);
    float ar = lr, ai = li;
#pragma unroll
    for (int q = 0; q < 6; q++) {
        float nr = ar * ar - ai * ai;
        float ni = 2.f * ar * ai;
        ar = nr; ai = ni;
    }
    float Sr = 0.f, Si = 0.f;
    for (int c = 0; c < cNC; c++) {
        const int idx = (er * cNC + c) * cD + d;
        g_cir[idx] = Sr;
        g_cii[idx] = Si;
        float nr = ar * Sr - ai * Si + g_cer[idx];
        float ni = ar * Si + ai * Sr + g_cei[idx];
        Sr = nr; Si = ni;
    }
}

// ---------------------------------------------------------------------------
// Scan pass3 — replay with carry, fused normalize + twist + 7 d-sums.
// Double-buffered smem reductions: ONE __syncthreads per timestep.
// ---------------------------------------------------------------------------
__global__ void scan_pass3(const float* __restrict__ ld_, const float* __restrict__ th_,
                           const float* __restrict__ Br_, const float* __restrict__ Bi_) {
    const int blk = blockIdx.x;
    const int c   = blk % cNC;
    const int er  = blk / cNC;
    const int b   = er / cER;
    const int erx = er % cER;
    const int d   = threadIdx.x;
    const int erd = erx * cD + d;
    const int lane = d & 31, warp = d >> 5;

    float lr, li; lambda_of(ld_, th_, erd, lr, li);
    const float Br = Br_[erd], Bi = Bi_[erd];

    const int cidx = (er * cNC + c) * cD + d;
    float hr = g_cir[cidx], hi = g_cii[cidx];

    __shared__ float sredp[2][8];
    __shared__ float sred7[2][8][7];

    const int t0 = c * cL;
    const int sbase = (b * cS) * (cER * 7) + erx * 7 + d;   // valid only d<7
    for (int t = t0; t < t0 + cL; t++) {
        float xr = g_sr[(b * cS + t) * cD + d];
        float xi = g_si[(b * cS + t) * cD + d];
        float ur = Br * xr - Bi * xi;
        float ui = Br * xi + Bi * xr;
        float nhr = lr * hr - li * hi + ur;
        float nhi = lr * hi + li * hr + ui;
        hr = nhr; hi = nhi;

        float v = hr * hr + hi * hi;
#pragma unroll
        for (int off = 16; off > 0; off >>= 1) v += __shfl_xor_sync(0xffffffffu, v, off);
        if (lane == 0) sredp[t & 1][warp] = v;
        __syncthreads();                        // publishes sredp[t&1] AND sred7[(t-1)&1]
        float tot = 0.f;
#pragma unroll
        for (int w = 0; w < 8; w++) tot += sredp[t & 1][w];
        const float inv = rsqrtf(tot * (1.0f / cD) + cEPS);

        const float nr = hr * inv, ni = hi * inv;
        const float thr_ = tanhf(nr), thi_ = tanhf(ni);
        const float gr_ = nr * (1.f + cIMP * thi_);
        const float gi_ = ni * (1.f + cIMP * thr_);

        float s[7];
        s[0] = gr_;          s[1] = gi_;
        s[2] = gr_ * gr_;    s[3] = gi_ * gi_;
        s[4] = gr_ * gi_;
        s[5] = tanhf(gr_);   s[6] = tanhf(gi_);
#pragma unroll
        for (int k = 0; k < 7; k++) {
            float u = s[k];
#pragma unroll
            for (int off = 16; off > 0; off >>= 1) u += __shfl_xor_sync(0xffffffffu, u, off);
            if (lane == 0) sred7[t & 1][warp][k] = u;
        }
        // readback for PREVIOUS timestep (its writes were published by this sync)
        if (t > t0 && d < 7) {
            const int tp = t - 1;
            float tk = 0.f;
#pragma unroll
            for (int w = 0; w < 8; w++) tk += sred7[tp & 1][w][d];
            g_S[sbase + tp * (cER * 7)] = tk;
        }
    }
    __syncthreads();
    if (d < 7) {
        const int tp = t0 + cL - 1;
        float tk = 0.f;
#pragma unroll
        for (int w = 0; w < 8; w++) tk += sred7[tp & 1][w][d];
        g_S[sbase + tp * (cER * 7)] = tk;
    }
}

// ---------------------------------------------------------------------------
// Mc = Wsh (complex) @ Wfus (complex) — 8-way k-split + reduce
// ---------------------------------------------------------------------------
__global__ void mc_part(const float* __restrict__ Wsh_r, const float* __restrict__ Wsh_i,
                        const float* __restrict__ Wfus_r, const float* __restrict__ Wfus_i) {
    const int j = blockIdx.x;      // e*14 + f
    const int seg = blockIdx.y;    // 0..7
    const int e = j / 14;
    const int tid = threadIdx.x;
    const float* wr = &Wsh_r[j * cH];
    const float* wi = &Wsh_i[j * cH];
    float accr[3] = {0.f, 0.f, 0.f}, acci[3] = {0.f, 0.f, 0.f};
    const int h0 = seg * 96;
    for (int h = h0; h < h0 + 96; h++) {
        const float ar = wr[h], ai = wi[h];
        const float* fr_row = &Wfus_r[(size_t)(e * cH + h) * cH];
        const float* fi_row = &Wfus_i[(size_t)(e * cH + h) * cH];
#pragma unroll
        for (int q = 0; q < 3; q++) {
            const int col = tid + q * 256;
            const float br = fr_row[col], bi = fi_row[col];
            accr[q] += ar * br - ai * bi;
            acci[q] += ar * bi + ai * br;
        }
    }
#pragma unroll
    for (int q = 0; q < 3; q++) {
        g_MpR[(seg * 28 + j) * cH + tid + q * 256] = accr[q];
        g_MpI[(seg * 28 + j) * cH + tid + q * 256] = acci[q];
    }
}

__global__ void mc_reduce() {
    const int idx = blockIdx.x * 256 + threadIdx.x;   // 28*768 = 21504
    const int j = idx / cH, col = idx % cH;
    float ar = 0.f, ai = 0.f;
#pragma unroll
    for (int seg = 0; seg < 8; seg++) {
        ar += g_MpR[(seg * 28 + j) * cH + col];
        ai += g_MpI[(seg * 28 + j) * cH + col];
    }
    g_Mr[j * cH + col] = ar;
    g_Mi[j * cH + col] = ai;
}

// ---------------------------------------------------------------------------
// bc = bfus + bsh(complex) @ Wfus(complex)
// ---------------------------------------------------------------------------
__global__ void bc_kernel(const float* __restrict__ bsh_r, const float* __restrict__ bsh_i,
                          const float* __restrict__ Wfus_r, const float* __restrict__ Wfus_i,
                          const float* __restrict__ bfus_r, const float* __restrict__ bfus_i) {
    const int c = blockIdx.x * blockDim.x + threadIdx.x;
    if (c >= cH) return;
    float ar = bfus_r[c], ai = bfus_i[c];
    for (int k = 0; k < cE * cH; k++) {
        const float br = bsh_r[k], bi = bsh_i[k];
        const float wr = Wfus_r[(size_t)k * cH + c], wi = Wfus_i[(size_t)k * cH + c];
        ar += br * wr - bi * wi;
        ai += br * wi + bi * wr;
    }
    g_bcr[c] = ar;
    g_bci[c] = ai;
}

// ---------------------------------------------------------------------------
// fuse — features from g_S, complex GEMM (K=28) with Mc; writes fur (fp32)
// and tf32-rounded fur/fui/z into A cols [768, 3072).
// ---------------------------------------------------------------------------
__global__ void fuse_kernel() {
    const int bs0 = blockIdx.x * 8;
    const int tid = threadIdx.x;

    __shared__ float Sh[8][56];
    __shared__ float frs[8][28], fis[8][28];

    for (int i = tid; i < 8 * 56; i += 256) {
        const int row = i / 56, q = i % 56;
        Sh[row][q] = g_S[(bs0 + row) * 56 + q];
    }
    __syncthreads();

    if (tid < 8 * 28) {
        const int row = tid / 28, j = tid % 28;
        const int e = j / 14, idx = j % 14;
        const float* Se = &Sh[row][e * 28];
        const float invD  = 1.0f / cD;
        const float invRD = 1.0f / (cR * cD);
        float fr = 0.f, fi = 0.f;
        if (idx < 4) {
            fr = Se[idx * 7 + 0] * invD;
            fi = Se[idx * 7 + 1] * invD;
        } else if (idx < 8) {
            const int r = idx - 4;
            fr = (Se[r * 7 + 2] - Se[r * 7 + 3]) * invD;
            fi = 2.f * Se[r * 7 + 4] * invD;
        } else {
            float T[7];
#pragma unroll
            for (int k = 0; k < 7; k++)
                T[k] = Se[k] + Se[7 + k] + Se[14 + k] + Se[21 + k];
            switch (idx) {
                case 8:  fr = T[0] * invRD;              fi = T[1] * invRD;              break;
                case 9:  fr = (T[2] - T[3]) * invRD;     fi = 2.f * T[4] * invRD;        break;
                case 10: fr = (T[2] + T[3]) * invRD;     fi = 0.f;                       break;
                case 11: fr = T[5] * invRD;              fi = T[6] * invRD;              break;
                case 12: fr = sqrtf(T[2] * invRD + cEPS); fi = sqrtf(T[3] * invRD + cEPS); break;
                default: fr = T[4] * invRD;              fi = 0.f;                       break;
            }
        }
        frs[row][j] = fr;
        fis[row][j] = fi;
    }
    __syncthreads();

    float ar[8][3], ai[8][3];
#pragma unroll
    for (int r = 0; r < 8; r++)
#pragma unroll
        for (int q = 0; q < 3; q++) { ar[r][q] = 0.f; ai[r][q] = 0.f; }

    for (int j = 0; j < 28; j++) {
        float mr[3], mi[3];
#pragma unroll
        for (int q = 0; q < 3; q++) {
            const int c = tid + q * 256;
            mr[q] = g_Mr[j * cH + c];
            mi[q] = g_Mi[j * cH + c];
        }
#pragma unroll
        for (int row = 0; row < 8; row++) {
            const float fr = frs[row][j], fi = fis[row][j];
#pragma unroll
            for (int q = 0; q < 3; q++) {
                ar[row][q] += fr * mr[q] - fi * mi[q];
                ai[row][q] += fr * mi[q] + fi * mr[q];
            }
        }
    }

#pragma unroll
    for (int q = 0; q < 3; q++) {
        const int c = tid + q * 256;
        const float bcr = g_bcr[c], bci = g_bci[c];
#pragma unroll
        for (int row = 0; row < 8; row++) {
            const float fur = ar[row][q] + bcr;
            const float fui = ai[row][q] + bci;
            const float z   = fur * (fui * sigmoidf_(fui));
            const size_t o  = (size_t)(bs0 + row) * cH + c;
            g_fur[o] = fur;
            const size_t ao = (size_t)(bs0 + row) * cKA;
            g_Atf[ao + 768 + c]  = tf32_round(fur);
            g_Atf[ao + 1536 + c] = tf32_round(fui);
            g_Atf[ao + 2304 + c] = tf32_round(z);
        }
    }
}

// ---------------------------------------------------------------------------
// launch
// ---------------------------------------------------------------------------
extern "C" void kernel_launch(void* const* d_in, const int* in_sizes, int n_in,
                              void* d_out, int out_size) {
    (void)in_sizes; (void)n_in; (void)out_size;
    const float* x       = (const float*)d_in[0];
    const float* Wsig_r  = (const float*)d_in[1];
    const float* Wsig_i  = (const float*)d_in[2];
    const float* bsig_r  = (const float*)d_in[3];
    const float* bsig_i  = (const float*)d_in[4];
    const float* log_dec = (const float*)d_in[5];
    const float* theta   = (const float*)d_in[6];
    const float* Bin_r   = (const float*)d_in[7];
    const float* Bin_i   = (const float*)d_in[8];
    const float* Wsh_r   = (const float*)d_in[9];
    const float* Wsh_i   = (const float*)d_in[10];
    const float* bsh_r   = (const float*)d_in[11];
    const float* bsh_i   = (const float*)d_in[12];
    const float* Wfus_r  = (const float*)d_in[13];
    const float* Wfus_i  = (const float*)d_in[14];
    const float* bfus_r  = (const float*)d_in[15];
    const float* bfus_i  = (const float*)d_in[16];
    const float* Wgate   = (const float*)d_in[17];
    const float* bgate   = (const float*)d_in[18];
    float* out = (float*)d_out;

    // dynamic smem for the tf32 gate (host attr, no allocation)
    cudaFuncSetAttribute(gate_tf32, cudaFuncAttributeMaxDynamicSharedMemorySize,
                         GATE_SMEM_BYTES);

    convert_x<<<cBS * cH / 4 / 256, 256>>>(x);
    prep_wgate<<<dim3(cKA / 32, cH / 32), dim3(32, 8)>>>(Wgate);

    // sig via validated fp32 SIMT GEMM (BK=16)
    sig_gemm<<<dim3(4, 64), 256>>>(x, Wsig_r, Wsig_i, bsig_r, bsig_i);

    scan_pass1<<<cBER * cNC, 256>>>(log_dec, theta, Bin_r, Bin_i);
    scan_pass2<<<cBER, 256>>>(log_dec, theta);
    scan_pass3<<<cBER * cNC, 256>>>(log_dec, theta, Bin_r, Bin_i);

    mc_part<<<dim3(28, 8), 256>>>(Wsh_r, Wsh_i, Wfus_r, Wfus_i);
    mc_reduce<<<28 * cH / 256, 256>>>();
    bc_kernel<<<3, 256>>>(bsh_r, bsh_i, Wfus_r, Wfus_i, bfus_r, bfus_i);
    fuse_kernel<<<cBS / 8, 256>>>();

    // gate: out = x + sigmoid([x|fur|fui|z] @ Wgate + bgate) * fur  (tf32 HMMA)
    gate_tf32<<<dim3(6, 64), 256, GATE_SMEM_BYTES>>>(x, bgate, out);
}